// round 12
// baseline (speedup 1.0000x reference)
#include <cuda_runtime.h>
#include <cstddef>

#define B_ 256
#define S_ 200
#define E_ 512
#define H_ 512

// ---- scratch (no allocations allowed) ----
__device__ float g_P[(size_t)B_ * S_ * H_];   // 104 MB: P[t][b][h]
__device__ float g_h[2][B_ * H_];             // h_t lives in g_h[t&1]
__device__ float g_pool[B_ * H_];             // time-mean of h
__device__ unsigned int g_flags[16 * 8 * 32]; // per (M-group, producer) counters, 128B apart

typedef unsigned long long u64;

__device__ __forceinline__ void fma2(u64 &c, u64 a, u64 b) {
    asm("fma.rn.f32x2 %0, %1, %2, %3;" : "=l"(c) : "l"(a), "l"(b), "l"(c));
}
__device__ __forceinline__ u64 splat2(float a) {
    u64 r; asm("mov.b64 %0, {%1, %1};" : "=l"(r) : "f"(a)); return r;
}
__device__ __forceinline__ float2 u2f(u64 v) {
    float2 r; asm("mov.b64 {%0, %1}, %2;" : "=f"(r.x), "=f"(r.y) : "l"(v)); return r;
}

// ============================================================================
// Kernel A: P = gather(emb, x) @ Wxh + (bxh + bhh)   (unchanged from R5)
// ============================================================================
#define PAST 36
#define PC_SMEM ((2 * 64 * PAST + 2 * 32 * 128) * 4)  // 51200 B

__global__ __launch_bounds__(256, 2) void precompute_kernel(
    const int* __restrict__ x, const float* __restrict__ emb,
    const float* __restrict__ Wxh, const float* __restrict__ bxh,
    const float* __restrict__ bhh)
{
    extern __shared__ float psm[];
    float* AsB = psm;                    // [2][64][PAST]
    float* WsB = psm + 2 * 64 * PAST;    // [2][32][128]

    const int n0 = blockIdx.x * 128;
    const int m0 = blockIdx.y * 64;
    const int t  = threadIdx.x;
    const int w  = t >> 5, l = t & 31;
    const int row0 = w * 8;
    const int c4 = 4 * l;

    const int arow  = t >> 3;
    const int aslot = (t & 7) * 4;
    const size_t e0 = (size_t)x[m0 + arow] * E_;
    const size_t e1 = (size_t)x[m0 + arow + 32] * E_;
    const int wrow = t >> 5;
    const int wcol = (t & 31) * 4;

    u64 acc[8][2];
#pragma unroll
    for (int i = 0; i < 8; i++) { acc[i][0] = 0ull; acc[i][1] = 0ull; }

    float4 pa0, pa1, pw0, pw1, pw2, pw3;
    pa0 = *(const float4*)&emb[e0 + aslot];
    pa1 = *(const float4*)&emb[e1 + aslot];
    pw0 = *(const float4*)&Wxh[(size_t)(0  + wrow) * H_ + n0 + wcol];
    pw1 = *(const float4*)&Wxh[(size_t)(8  + wrow) * H_ + n0 + wcol];
    pw2 = *(const float4*)&Wxh[(size_t)(16 + wrow) * H_ + n0 + wcol];
    pw3 = *(const float4*)&Wxh[(size_t)(24 + wrow) * H_ + n0 + wcol];
    *(float4*)&AsB[arow * PAST + aslot]        = pa0;
    *(float4*)&AsB[(arow + 32) * PAST + aslot] = pa1;
    *(float4*)&WsB[(0  + wrow) * 128 + wcol] = pw0;
    *(float4*)&WsB[(8  + wrow) * 128 + wcol] = pw1;
    *(float4*)&WsB[(16 + wrow) * 128 + wcol] = pw2;
    *(float4*)&WsB[(24 + wrow) * 128 + wcol] = pw3;
    __syncthreads();

#pragma unroll 1
    for (int ch = 0; ch < 16; ch++) {
        if (ch < 15) {
            const int kn = (ch + 1) * 32;
            pa0 = *(const float4*)&emb[e0 + kn + aslot];
            pa1 = *(const float4*)&emb[e1 + kn + aslot];
            pw0 = *(const float4*)&Wxh[(size_t)(kn + wrow) * H_ + n0 + wcol];
            pw1 = *(const float4*)&Wxh[(size_t)(kn + 8  + wrow) * H_ + n0 + wcol];
            pw2 = *(const float4*)&Wxh[(size_t)(kn + 16 + wrow) * H_ + n0 + wcol];
            pw3 = *(const float4*)&Wxh[(size_t)(kn + 24 + wrow) * H_ + n0 + wcol];
        }
        const float* Ab = AsB + (ch & 1) * (64 * PAST);
        const float* Wb = WsB + (ch & 1) * (32 * 128);

#pragma unroll
        for (int kg = 0; kg < 8; kg++) {
            float4 a0 = *(const float4*)&Ab[(row0 + 0) * PAST + kg * 4];
            float4 a1 = *(const float4*)&Ab[(row0 + 1) * PAST + kg * 4];
            float4 a2 = *(const float4*)&Ab[(row0 + 2) * PAST + kg * 4];
            float4 a3 = *(const float4*)&Ab[(row0 + 3) * PAST + kg * 4];
            float4 a4 = *(const float4*)&Ab[(row0 + 4) * PAST + kg * 4];
            float4 a5 = *(const float4*)&Ab[(row0 + 5) * PAST + kg * 4];
            float4 a6 = *(const float4*)&Ab[(row0 + 6) * PAST + kg * 4];
            float4 a7 = *(const float4*)&Ab[(row0 + 7) * PAST + kg * 4];
#define PKJ(j, comp) {                                              \
            const u64* wp = (const u64*)&Wb[(kg * 4 + (j)) * 128 + c4]; \
            u64 w01 = wp[0], w23 = wp[1];                           \
            fma2(acc[0][0], splat2(a0.comp), w01); fma2(acc[0][1], splat2(a0.comp), w23); \
            fma2(acc[1][0], splat2(a1.comp), w01); fma2(acc[1][1], splat2(a1.comp), w23); \
            fma2(acc[2][0], splat2(a2.comp), w01); fma2(acc[2][1], splat2(a2.comp), w23); \
            fma2(acc[3][0], splat2(a3.comp), w01); fma2(acc[3][1], splat2(a3.comp), w23); \
            fma2(acc[4][0], splat2(a4.comp), w01); fma2(acc[4][1], splat2(a4.comp), w23); \
            fma2(acc[5][0], splat2(a5.comp), w01); fma2(acc[5][1], splat2(a5.comp), w23); \
            fma2(acc[6][0], splat2(a6.comp), w01); fma2(acc[6][1], splat2(a6.comp), w23); \
            fma2(acc[7][0], splat2(a7.comp), w01); fma2(acc[7][1], splat2(a7.comp), w23); }
            PKJ(0, x) PKJ(1, y) PKJ(2, z) PKJ(3, w)
#undef PKJ
        }

        if (ch < 15) {
            float* An = AsB + ((ch + 1) & 1) * (64 * PAST);
            float* Wn = WsB + ((ch + 1) & 1) * (32 * 128);
            *(float4*)&An[arow * PAST + aslot]        = pa0;
            *(float4*)&An[(arow + 32) * PAST + aslot] = pa1;
            *(float4*)&Wn[(0  + wrow) * 128 + wcol] = pw0;
            *(float4*)&Wn[(8  + wrow) * 128 + wcol] = pw1;
            *(float4*)&Wn[(16 + wrow) * 128 + wcol] = pw2;
            *(float4*)&Wn[(24 + wrow) * 128 + wcol] = pw3;
            __syncthreads();
        }
    }

    float4 bxv = *(const float4*)&bxh[n0 + c4];
    float4 bhv = *(const float4*)&bhh[n0 + c4];
    const float b0 = bxv.x + bhv.x, b1 = bxv.y + bhv.y;
    const float b2 = bxv.z + bhv.z, b3 = bxv.w + bhv.w;
#pragma unroll
    for (int i = 0; i < 8; i++) {
        float2 v0 = u2f(acc[i][0]);
        float2 v1 = u2f(acc[i][1]);
        float4 o; o.x = v0.x + b0; o.y = v0.y + b1; o.z = v1.x + b2; o.w = v1.y + b3;
        int m = m0 + row0 + i;
        int bb = m / S_;
        int tt = m - bb * S_;
        *(float4*)&g_P[((size_t)tt * B_ + bb) * H_ + n0 + c4] = o;
    }
}

// ============================================================================
// Kernel B: persistent RNN — producer flags + K-slice pipelined exchange.
// 128 CTAs = 16 M-groups x 8 ranks (64-col slices). Whh slice 128KB smem.
// Per step: publish own slice (STG + flag++), then for each peer slice:
// spin its flag, LDG the 4KB slice (1 float4/thread), compute PREVIOUS slice
// (hides LDG), STS, sync. No group-wide barrier; skew absorbed per stage.
// Thread map: warp w: rows 4*(w&3).., cols 32*(w>>2)..; thread = 1 row x 4 col.
// ============================================================================
#define AST 520
#define RNN_SMEM ((H_ * 64 + 16 * AST) * 4)  // 131072 + 33280 = 164352 B

#define SLICE_COMPUTE(rr) {                                                  \
    const float* ap_ = myAp + (rr) * 64;                                     \
    const float* wp_ = &Ws[(rr) * 4096 + c4];                                \
    _Pragma("unroll")                                                        \
    for (int kk = 0; kk < 64; kk += 4) {                                     \
        float4 Av = *(const float4*)(ap_ + kk);                              \
        ulonglong2 wv;                                                       \
        wv = *(const ulonglong2*)(wp_);                                      \
        fma2(a0, splat2(Av.x), wv.x); fma2(a1, splat2(Av.x), wv.y);          \
        wv = *(const ulonglong2*)(wp_ + 64);                                 \
        fma2(a0, splat2(Av.y), wv.x); fma2(a1, splat2(Av.y), wv.y);          \
        wv = *(const ulonglong2*)(wp_ + 128);                                \
        fma2(a0, splat2(Av.z), wv.x); fma2(a1, splat2(Av.z), wv.y);          \
        wv = *(const ulonglong2*)(wp_ + 192);                                \
        fma2(a0, splat2(Av.w), wv.x); fma2(a1, splat2(Av.w), wv.y);          \
        wp_ += 256;                                                          \
    } }

__global__ __launch_bounds__(256, 1) void rnn_kernel(const float* __restrict__ Whh)
{
    extern __shared__ float sm[];
    float* Ws = sm;               // [512][64] Whh slice (stationary)
    float* As = sm + H_ * 64;     // [16][AST] current h rows

    const int cta  = blockIdx.x;
    const int mg   = cta >> 3;
    const int rank = cta & 7;
    const int m0   = mg * 16;
    const int n0   = rank * 64;
    const int t    = threadIdx.x;
    const int w    = t >> 5, l = t & 31;
    const int row  = 4 * (w & 3) + (l >> 3);     // 0..15
    const int c4   = 32 * (w >> 2) + 4 * (l & 7); // 0..60 (local col)

    // slice staging map: thread t covers (srow, sk4) of a 16x64 slice
    const int srow = t >> 4;
    const int sk4  = (t & 15) * 4;

    // Load Whh[:, n0:n0+64] into smem (8192 float4 / 256 thr = 32 reps).
#pragma unroll 8
    for (int rep = 0; rep < 32; rep++) {
        int i4 = rep * 256 + t;
        int k  = i4 >> 4;
        int j4 = (i4 & 15) * 4;
        *(float4*)&Ws[k * 64 + j4] = *(const float4*)&Whh[(size_t)k * H_ + n0 + j4];
    }
    // h_0 = 0: zero the staging buffer (step 0 reads zeros)
    for (int i = t; i < 16 * AST; i += 256) As[i] = 0.0f;
    __syncthreads();

    float4 ps = {0, 0, 0, 0};

    const size_t pstride = (size_t)B_ * H_;
    const size_t pb = (size_t)(m0 + row) * H_ + n0 + c4;   // P/h/pool address
    ulonglong2 pA = *(const ulonglong2*)&g_P[pb];

    unsigned* const fbase = &g_flags[mg * 8 * 32];
    const float* const myAp = &As[row * AST];
    const size_t sgbase = (size_t)(m0 + srow) * H_ + sk4;  // + r*64 for slice r

    for (int step = 0; step < S_; step++) {
        u64 a0 = pA.x, a1 = pA.y;
        if (step + 1 < S_)   // prefetch next P early (independent of recurrence)
            pA = *(const ulonglong2*)&g_P[pb + (size_t)(step + 1) * pstride];

        const float* hsrc = g_h[step & 1];
        int rprev = rank;   // own slice already staged (end of prev step / zeros)

#pragma unroll 1
        for (int i = 1; i < 8; i++) {
            const int r = (rank + i) & 7;
            // spin on producer r's flag (all threads; same addr -> 1 req/warp)
            if (step > 0) {
                unsigned* fp = fbase + r * 32;
                unsigned v;
                do {
                    asm volatile("ld.acquire.gpu.u32 %0, [%1];" : "=r"(v) : "l"(fp) : "memory");
                } while (v < (unsigned)step);
            }
            // issue slice LDG, hide it behind previous slice's compute
            float4 hv = *(const float4*)&hsrc[sgbase + (size_t)r * 64];
            SLICE_COMPUTE(rprev);
            *(float4*)&As[srow * AST + r * 64 + sk4] = hv;
            __syncthreads();
            rprev = r;
        }
        SLICE_COMPUTE(rprev);

        // relu + pool
        float2 v0 = u2f(a0), v1 = u2f(a1);
        float4 o;
        o.x = fmaxf(v0.x, 0.f); o.y = fmaxf(v0.y, 0.f);
        o.z = fmaxf(v1.x, 0.f); o.w = fmaxf(v1.y, 0.f);
        ps.x += o.x; ps.y += o.y; ps.z += o.z; ps.w += o.w;

        if (step + 1 < S_) {
            // publish own slice: global (for peers) + smem (for ourselves)
            float* hdst = g_h[(step + 1) & 1];
            *(float4*)&hdst[pb] = o;
            *(float4*)&As[row * AST + rank * 64 + c4] = o;
            __syncthreads();   // all STGs issued + own slice visible in smem
            if (t == 0) {
                unsigned* fp = fbase + rank * 32;
                asm volatile("red.release.gpu.add.u32 [%0], 1;" :: "l"(fp) : "memory");
            }
        }
    }

    const float inv = 1.0f / (float)S_;
    float4 qv;
    qv.x = ps.x * inv; qv.y = ps.y * inv; qv.z = ps.z * inv; qv.w = ps.w * inv;
    *(float4*)&g_pool[pb] = qv;
}

// ============================================================================
// Kernel C: out = pooled @ Wfc + bfc
// ============================================================================
__global__ __launch_bounds__(128) void fc_kernel(const float* __restrict__ Wfc,
                                                 const float* __restrict__ bfc,
                                                 float* __restrict__ out)
{
    const int b = blockIdx.x;
    const int t = threadIdx.x;
    float s0 = 0, s1 = 0, s2 = 0, s3 = 0;
    const float* pr = &g_pool[(size_t)b * H_];
    for (int k = t; k < H_; k += 128) {
        float v = pr[k];
        float4 wv = *(const float4*)&Wfc[k * 4];
        s0 += v * wv.x; s1 += v * wv.y; s2 += v * wv.z; s3 += v * wv.w;
    }
#pragma unroll
    for (int o = 16; o > 0; o >>= 1) {
        s0 += __shfl_down_sync(0xffffffffu, s0, o);
        s1 += __shfl_down_sync(0xffffffffu, s1, o);
        s2 += __shfl_down_sync(0xffffffffu, s2, o);
        s3 += __shfl_down_sync(0xffffffffu, s3, o);
    }
    __shared__ float red[4][4];
    if ((t & 31) == 0) {
        int wrp = t >> 5;
        red[wrp][0] = s0; red[wrp][1] = s1; red[wrp][2] = s2; red[wrp][3] = s3;
    }
    __syncthreads();
    if (t < 4) {
        out[b * 4 + t] = red[0][t] + red[1][t] + red[2][t] + red[3][t] + bfc[t];
    }
}

// ============================================================================
extern "C" void kernel_launch(void* const* d_in, const int* in_sizes, int n_in,
                              void* d_out, int out_size)
{
    const int*   x   = (const int*)d_in[0];
    const float* emb = (const float*)d_in[1];
    const float* Wxh = (const float*)d_in[2];
    const float* bxh = (const float*)d_in[3];
    const float* Whh = (const float*)d_in[4];
    const float* bhh = (const float*)d_in[5];
    const float* Wfc = (const float*)d_in[6];
    const float* bfc = (const float*)d_in[7];
    float* out = (float*)d_out;

    void *hAddr = nullptr, *flagAddr = nullptr;
    cudaGetSymbolAddress(&hAddr, g_h);
    cudaGetSymbolAddress(&flagAddr, g_flags);
    cudaMemsetAsync(hAddr, 0, sizeof(float) * 2 * B_ * H_);
    cudaMemsetAsync(flagAddr, 0, sizeof(unsigned) * 16 * 8 * 32);

    cudaFuncSetAttribute(precompute_kernel, cudaFuncAttributeMaxDynamicSharedMemorySize, PC_SMEM);
    cudaFuncSetAttribute(rnn_kernel, cudaFuncAttributeMaxDynamicSharedMemorySize, RNN_SMEM);

    precompute_kernel<<<dim3(4, 800), 256, PC_SMEM>>>(x, emb, Wxh, bxh, bhh);
    rnn_kernel<<<128, 256, RNN_SMEM>>>(Whh);
    fc_kernel<<<B_, 128>>>(Wfc, bfc, out);
}

// round 13
// speedup vs baseline: 1.2554x; 1.2554x over previous
#include <cuda_runtime.h>
#include <cstddef>

#define B_ 256
#define S_ 200
#define E_ 512
#define H_ 512

// ---- scratch (no allocations allowed) ----
__device__ float g_P[(size_t)B_ * S_ * H_];   // 104 MB: P[t][b][h]
__device__ float g_h[2][B_ * H_];             // h_t lives in g_h[t&1]
__device__ float g_pool[B_ * H_];             // time-mean of h
__device__ unsigned int g_flags[16 * 32];     // per-group step counters (128B apart)

typedef unsigned long long u64;

__device__ __forceinline__ void fma2(u64 &c, u64 a, u64 b) {
    asm("fma.rn.f32x2 %0, %1, %2, %3;" : "=l"(c) : "l"(a), "l"(b), "l"(c));
}
__device__ __forceinline__ u64 splat2(float a) {
    u64 r; asm("mov.b64 %0, {%1, %1};" : "=l"(r) : "f"(a)); return r;
}
__device__ __forceinline__ float2 u2f(u64 v) {
    float2 r; asm("mov.b64 {%0, %1}, %2;" : "=f"(r.x), "=f"(r.y) : "l"(v)); return r;
}

// ============================================================================
// Kernel A: P = gather(emb, x) @ Wxh + (bxh + bhh)   (unchanged from R5)
// ============================================================================
#define PAST 36
#define PC_SMEM ((2 * 64 * PAST + 2 * 32 * 128) * 4)  // 51200 B

__global__ __launch_bounds__(256, 2) void precompute_kernel(
    const int* __restrict__ x, const float* __restrict__ emb,
    const float* __restrict__ Wxh, const float* __restrict__ bxh,
    const float* __restrict__ bhh)
{
    extern __shared__ float psm[];
    float* AsB = psm;                    // [2][64][PAST]
    float* WsB = psm + 2 * 64 * PAST;    // [2][32][128]

    const int n0 = blockIdx.x * 128;
    const int m0 = blockIdx.y * 64;
    const int t  = threadIdx.x;
    const int w  = t >> 5, l = t & 31;
    const int row0 = w * 8;
    const int c4 = 4 * l;

    const int arow  = t >> 3;
    const int aslot = (t & 7) * 4;
    const size_t e0 = (size_t)x[m0 + arow] * E_;
    const size_t e1 = (size_t)x[m0 + arow + 32] * E_;
    const int wrow = t >> 5;
    const int wcol = (t & 31) * 4;

    u64 acc[8][2];
#pragma unroll
    for (int i = 0; i < 8; i++) { acc[i][0] = 0ull; acc[i][1] = 0ull; }

    float4 pa0, pa1, pw0, pw1, pw2, pw3;
    pa0 = *(const float4*)&emb[e0 + aslot];
    pa1 = *(const float4*)&emb[e1 + aslot];
    pw0 = *(const float4*)&Wxh[(size_t)(0  + wrow) * H_ + n0 + wcol];
    pw1 = *(const float4*)&Wxh[(size_t)(8  + wrow) * H_ + n0 + wcol];
    pw2 = *(const float4*)&Wxh[(size_t)(16 + wrow) * H_ + n0 + wcol];
    pw3 = *(const float4*)&Wxh[(size_t)(24 + wrow) * H_ + n0 + wcol];
    *(float4*)&AsB[arow * PAST + aslot]        = pa0;
    *(float4*)&AsB[(arow + 32) * PAST + aslot] = pa1;
    *(float4*)&WsB[(0  + wrow) * 128 + wcol] = pw0;
    *(float4*)&WsB[(8  + wrow) * 128 + wcol] = pw1;
    *(float4*)&WsB[(16 + wrow) * 128 + wcol] = pw2;
    *(float4*)&WsB[(24 + wrow) * 128 + wcol] = pw3;
    __syncthreads();

#pragma unroll 1
    for (int ch = 0; ch < 16; ch++) {
        if (ch < 15) {
            const int kn = (ch + 1) * 32;
            pa0 = *(const float4*)&emb[e0 + kn + aslot];
            pa1 = *(const float4*)&emb[e1 + kn + aslot];
            pw0 = *(const float4*)&Wxh[(size_t)(kn + wrow) * H_ + n0 + wcol];
            pw1 = *(const float4*)&Wxh[(size_t)(kn + 8  + wrow) * H_ + n0 + wcol];
            pw2 = *(const float4*)&Wxh[(size_t)(kn + 16 + wrow) * H_ + n0 + wcol];
            pw3 = *(const float4*)&Wxh[(size_t)(kn + 24 + wrow) * H_ + n0 + wcol];
        }
        const float* Ab = AsB + (ch & 1) * (64 * PAST);
        const float* Wb = WsB + (ch & 1) * (32 * 128);

#pragma unroll
        for (int kg = 0; kg < 8; kg++) {
            float4 a0 = *(const float4*)&Ab[(row0 + 0) * PAST + kg * 4];
            float4 a1 = *(const float4*)&Ab[(row0 + 1) * PAST + kg * 4];
            float4 a2 = *(const float4*)&Ab[(row0 + 2) * PAST + kg * 4];
            float4 a3 = *(const float4*)&Ab[(row0 + 3) * PAST + kg * 4];
            float4 a4 = *(const float4*)&Ab[(row0 + 4) * PAST + kg * 4];
            float4 a5 = *(const float4*)&Ab[(row0 + 5) * PAST + kg * 4];
            float4 a6 = *(const float4*)&Ab[(row0 + 6) * PAST + kg * 4];
            float4 a7 = *(const float4*)&Ab[(row0 + 7) * PAST + kg * 4];
#define PKJ(j, comp) {                                              \
            const u64* wp = (const u64*)&Wb[(kg * 4 + (j)) * 128 + c4]; \
            u64 w01 = wp[0], w23 = wp[1];                           \
            fma2(acc[0][0], splat2(a0.comp), w01); fma2(acc[0][1], splat2(a0.comp), w23); \
            fma2(acc[1][0], splat2(a1.comp), w01); fma2(acc[1][1], splat2(a1.comp), w23); \
            fma2(acc[2][0], splat2(a2.comp), w01); fma2(acc[2][1], splat2(a2.comp), w23); \
            fma2(acc[3][0], splat2(a3.comp), w01); fma2(acc[3][1], splat2(a3.comp), w23); \
            fma2(acc[4][0], splat2(a4.comp), w01); fma2(acc[4][1], splat2(a4.comp), w23); \
            fma2(acc[5][0], splat2(a5.comp), w01); fma2(acc[5][1], splat2(a5.comp), w23); \
            fma2(acc[6][0], splat2(a6.comp), w01); fma2(acc[6][1], splat2(a6.comp), w23); \
            fma2(acc[7][0], splat2(a7.comp), w01); fma2(acc[7][1], splat2(a7.comp), w23); }
            PKJ(0, x) PKJ(1, y) PKJ(2, z) PKJ(3, w)
#undef PKJ
        }

        if (ch < 15) {
            float* An = AsB + ((ch + 1) & 1) * (64 * PAST);
            float* Wn = WsB + ((ch + 1) & 1) * (32 * 128);
            *(float4*)&An[arow * PAST + aslot]        = pa0;
            *(float4*)&An[(arow + 32) * PAST + aslot] = pa1;
            *(float4*)&Wn[(0  + wrow) * 128 + wcol] = pw0;
            *(float4*)&Wn[(8  + wrow) * 128 + wcol] = pw1;
            *(float4*)&Wn[(16 + wrow) * 128 + wcol] = pw2;
            *(float4*)&Wn[(24 + wrow) * 128 + wcol] = pw3;
            __syncthreads();
        }
    }

    float4 bxv = *(const float4*)&bxh[n0 + c4];
    float4 bhv = *(const float4*)&bhh[n0 + c4];
    const float b0 = bxv.x + bhv.x, b1 = bxv.y + bhv.y;
    const float b2 = bxv.z + bhv.z, b3 = bxv.w + bhv.w;
#pragma unroll
    for (int i = 0; i < 8; i++) {
        float2 v0 = u2f(acc[i][0]);
        float2 v1 = u2f(acc[i][1]);
        float4 o; o.x = v0.x + b0; o.y = v0.y + b1; o.z = v1.x + b2; o.w = v1.y + b3;
        int m = m0 + row0 + i;
        int bb = m / S_;
        int tt = m - bb * S_;
        *(float4*)&g_P[((size_t)tt * B_ + bb) * H_ + n0 + c4] = o;
    }
}

// ============================================================================
// Kernel B: persistent RNN — TWO independent M-groups interleaved per CTA.
// 128 CTAs = 8 pairs x 16 ranks (32 cols). Warps 0-3 -> group 2p, warps 4-7
// -> group 2p+1, computed CONCURRENTLY (independent recurrences) so the
// global h exchange of one group hides behind the other's compute.
// W layout: Wp[cpair][k] as u64 (col-pair-major) -> LDS.128 = W for 2 k's.
// Thread = 2 rows x 2 cols: per warp per 4k: 2 W-wf + 2 A-wf vs 16 fma cyc.
// Publish: STG h + red group counter; consume: t0 spins, restage to smem.
// ============================================================================
#define WST 514   // u64 stride for Wp rows (16B bank shift per cpair)
#define AST 516   // float stride for h staging rows
#define RNN_SMEM (16 * WST * 8 + 2 * 16 * AST * 4)  // 65792 + 66048 = 131840 B

__global__ __launch_bounds__(256, 1) void rnn_kernel(const float* __restrict__ Whh)
{
    extern __shared__ char smraw[];
    u64*   Wp  = (u64*)smraw;                       // [16][WST] u64
    float* AsA = (float*)(smraw + 16 * WST * 8);    // [16][AST]
    float* AsB = AsA + 16 * AST;                    // [16][AST]

    const int p  = blockIdx.x >> 4;       // group-pair 0..7
    const int r  = blockIdx.x & 15;       // N-rank 0..15
    const int n0 = 32 * r;
    const int t  = threadIdx.x;
    const int w  = t >> 5, l = t & 31;
    const int grp = w >> 2;               // 0 = group 2p, 1 = group 2p+1
    const int wg  = w & 3;                // warp-in-half
    const int g   = 2 * p + grp;          // my M-group
    const int rp  = l >> 3;               // 0..3 row-pair within warp
    const int cp  = (l & 7) + 8 * (wg >> 1);   // 0..15 col-pair
    const int row0 = 8 * (wg & 1) + 2 * rp;    // 0..14 (even), local row
    float* As = grp ? AsB : AsA;

    const int grow0 = g * 16 + row0;      // global batch row (and grow0+1)
    const int gcol  = n0 + 2 * cp;        // global h column (pair)

    // ---- load Whh slice col-pair-major: Wp[cp][k] = (Whh[k][gcol], [k][gcol+1])
    for (int idx = t; idx < 16 * 512; idx += 256) {
        int cpi = idx & 15, k = idx >> 4;
        Wp[cpi * WST + k] = *(const u64*)&Whh[(size_t)k * H_ + n0 + 2 * cpi];
    }
    // h(0) = 0
    for (int i = t; i < 16 * AST; i += 256) { AsA[i] = 0.0f; AsB[i] = 0.0f; }
    __syncthreads();

    float2 ps0 = {0, 0}, ps1 = {0, 0};

    const size_t pstride = (size_t)B_ * H_;
    const size_t pb0 = (size_t)grow0 * H_ + gcol;        // + step*pstride
    const size_t pb1 = pb0 + H_;
    u64 pP0 = *(const u64*)&g_P[pb0];
    u64 pP1 = *(const u64*)&g_P[pb1];

    unsigned* const cntA = &g_flags[(2 * p) * 32];
    unsigned* const cntB = &g_flags[(2 * p + 1) * 32];

    const int ht = t & 127;               // thread id within half
    const int gbase = g * 16;

    for (int step = 0; step < S_; step++) {
        u64 acc0 = pP0, acc1 = pP1;
        if (step + 1 < S_) {              // prefetch next P (independent)
            const size_t po = (size_t)(step + 1) * pstride;
            pP0 = *(const u64*)&g_P[pb0 + po];
            pP1 = *(const u64*)&g_P[pb1 + po];
        }

        const float* ap0 = As + row0 * AST;
        const float* ap1 = ap0 + AST;
        const u64*  wp  = Wp + cp * WST;
#pragma unroll 4
        for (int k = 0; k < H_; k += 4) {
            float4 A0 = *(const float4*)(ap0 + k);
            float4 A1 = *(const float4*)(ap1 + k);
            ulonglong2 w01 = *(const ulonglong2*)(wp + k);
            ulonglong2 w23 = *(const ulonglong2*)(wp + k + 2);
            fma2(acc0, splat2(A0.x), w01.x); fma2(acc1, splat2(A1.x), w01.x);
            fma2(acc0, splat2(A0.y), w01.y); fma2(acc1, splat2(A1.y), w01.y);
            fma2(acc0, splat2(A0.z), w23.x); fma2(acc1, splat2(A1.z), w23.x);
            fma2(acc0, splat2(A0.w), w23.y); fma2(acc1, splat2(A1.w), w23.y);
        }

        // relu + pool + publish
        float2 o0 = u2f(acc0), o1 = u2f(acc1);
        o0.x = fmaxf(o0.x, 0.f); o0.y = fmaxf(o0.y, 0.f);
        o1.x = fmaxf(o1.x, 0.f); o1.y = fmaxf(o1.y, 0.f);
        ps0.x += o0.x; ps0.y += o0.y; ps1.x += o1.x; ps1.y += o1.y;

        float* hdst = g_h[(step + 1) & 1];
        *(float2*)&hdst[pb0] = o0;
        *(float2*)&hdst[pb1] = o1;
        __syncthreads();                   // all 256 threads' STGs before flags
        if (t == 0) {
            asm volatile("red.release.gpu.add.u32 [%0], 1;" :: "l"(cntA) : "memory");
            asm volatile("red.release.gpu.add.u32 [%0], 1;" :: "l"(cntB) : "memory");
        }

        if (step + 1 < S_) {
            if (t == 0) {
                const unsigned tgt = 16u * (unsigned)(step + 1);
                unsigned v;
                do { asm volatile("ld.acquire.gpu.u32 %0, [%1];" : "=r"(v) : "l"(cntA) : "memory"); } while (v < tgt);
                do { asm volatile("ld.acquire.gpu.u32 %0, [%1];" : "=r"(v) : "l"(cntB) : "memory"); } while (v < tgt);
            }
            __syncthreads();
            // each half restages its own group's 16x512 h rows
            const float* hsrc = g_h[(step + 1) & 1];
#pragma unroll
            for (int rep = 0; rep < 16; rep++) {
                int i4   = rep * 128 + ht;
                int arow = i4 >> 7;
                int k4   = (i4 & 127) * 4;
                *(float4*)&As[arow * AST + k4] =
                    *(const float4*)&hsrc[(size_t)(gbase + arow) * H_ + k4];
            }
            __syncthreads();
        }
    }

    const float inv = 1.0f / (float)S_;
    float2 q;
    q.x = ps0.x * inv; q.y = ps0.y * inv; *(float2*)&g_pool[pb0] = q;
    q.x = ps1.x * inv; q.y = ps1.y * inv; *(float2*)&g_pool[pb1] = q;
}

// ============================================================================
// Kernel C: out = pooled @ Wfc + bfc
// ============================================================================
__global__ __launch_bounds__(128) void fc_kernel(const float* __restrict__ Wfc,
                                                 const float* __restrict__ bfc,
                                                 float* __restrict__ out)
{
    const int b = blockIdx.x;
    const int t = threadIdx.x;
    float s0 = 0, s1 = 0, s2 = 0, s3 = 0;
    const float* pr = &g_pool[(size_t)b * H_];
    for (int k = t; k < H_; k += 128) {
        float v = pr[k];
        float4 wv = *(const float4*)&Wfc[k * 4];
        s0 += v * wv.x; s1 += v * wv.y; s2 += v * wv.z; s3 += v * wv.w;
    }
#pragma unroll
    for (int o = 16; o > 0; o >>= 1) {
        s0 += __shfl_down_sync(0xffffffffu, s0, o);
        s1 += __shfl_down_sync(0xffffffffu, s1, o);
        s2 += __shfl_down_sync(0xffffffffu, s2, o);
        s3 += __shfl_down_sync(0xffffffffu, s3, o);
    }
    __shared__ float red[4][4];
    if ((t & 31) == 0) {
        int wrp = t >> 5;
        red[wrp][0] = s0; red[wrp][1] = s1; red[wrp][2] = s2; red[wrp][3] = s3;
    }
    __syncthreads();
    if (t < 4) {
        out[b * 4 + t] = red[0][t] + red[1][t] + red[2][t] + red[3][t] + bfc[t];
    }
}

// ============================================================================
extern "C" void kernel_launch(void* const* d_in, const int* in_sizes, int n_in,
                              void* d_out, int out_size)
{
    const int*   x   = (const int*)d_in[0];
    const float* emb = (const float*)d_in[1];
    const float* Wxh = (const float*)d_in[2];
    const float* bxh = (const float*)d_in[3];
    const float* Whh = (const float*)d_in[4];
    const float* bhh = (const float*)d_in[5];
    const float* Wfc = (const float*)d_in[6];
    const float* bfc = (const float*)d_in[7];
    float* out = (float*)d_out;

    void *hAddr = nullptr, *flagAddr = nullptr;
    cudaGetSymbolAddress(&hAddr, g_h);
    cudaGetSymbolAddress(&flagAddr, g_flags);
    cudaMemsetAsync(hAddr, 0, sizeof(float) * 2 * B_ * H_);
    cudaMemsetAsync(flagAddr, 0, sizeof(unsigned) * 16 * 32);

    cudaFuncSetAttribute(precompute_kernel, cudaFuncAttributeMaxDynamicSharedMemorySize, PC_SMEM);
    cudaFuncSetAttribute(rnn_kernel, cudaFuncAttributeMaxDynamicSharedMemorySize, RNN_SMEM);

    precompute_kernel<<<dim3(4, 800), 256, PC_SMEM>>>(x, emb, Wxh, bxh, bhh);
    rnn_kernel<<<128, 256, RNN_SMEM>>>(Whh);
    fc_kernel<<<B_, 128>>>(Wfc, bfc, out);
}

// round 14
// speedup vs baseline: 1.3138x; 1.0465x over previous
#include <cuda_runtime.h>
#include <cstddef>

#define B_ 256
#define S_ 200
#define E_ 512
#define H_ 512

// ---- scratch (no allocations allowed) ----
__device__ float g_P[(size_t)B_ * S_ * H_];   // 104 MB: P[t][b][h]
__device__ float g_h[2][B_ * H_];             // h_t lives in g_h[t&1]
__device__ float g_pool[B_ * H_];             // time-mean of h
__device__ unsigned int g_flags[16 * 32];     // per-group step counters (128B apart)

typedef unsigned long long u64;

__device__ __forceinline__ void fma2(u64 &c, u64 a, u64 b) {
    asm("fma.rn.f32x2 %0, %1, %2, %3;" : "=l"(c) : "l"(a), "l"(b), "l"(c));
}
__device__ __forceinline__ u64 splat2(float a) {
    u64 r; asm("mov.b64 %0, {%1, %1};" : "=l"(r) : "f"(a)); return r;
}
__device__ __forceinline__ float2 u2f(u64 v) {
    float2 r; asm("mov.b64 {%0, %1}, %2;" : "=f"(r.x), "=f"(r.y) : "l"(v)); return r;
}

// ============================================================================
// Kernel A: P = gather(emb, x) @ Wxh + (bxh + bhh)   (unchanged from R5)
// ============================================================================
#define PAST 36
#define PC_SMEM ((2 * 64 * PAST + 2 * 32 * 128) * 4)  // 51200 B

__global__ __launch_bounds__(256, 2) void precompute_kernel(
    const int* __restrict__ x, const float* __restrict__ emb,
    const float* __restrict__ Wxh, const float* __restrict__ bxh,
    const float* __restrict__ bhh)
{
    extern __shared__ float psm[];
    float* AsB = psm;                    // [2][64][PAST]
    float* WsB = psm + 2 * 64 * PAST;    // [2][32][128]

    const int n0 = blockIdx.x * 128;
    const int m0 = blockIdx.y * 64;
    const int t  = threadIdx.x;
    const int w  = t >> 5, l = t & 31;
    const int row0 = w * 8;
    const int c4 = 4 * l;

    const int arow  = t >> 3;
    const int aslot = (t & 7) * 4;
    const size_t e0 = (size_t)x[m0 + arow] * E_;
    const size_t e1 = (size_t)x[m0 + arow + 32] * E_;
    const int wrow = t >> 5;
    const int wcol = (t & 31) * 4;

    u64 acc[8][2];
#pragma unroll
    for (int i = 0; i < 8; i++) { acc[i][0] = 0ull; acc[i][1] = 0ull; }

    float4 pa0, pa1, pw0, pw1, pw2, pw3;
    pa0 = *(const float4*)&emb[e0 + aslot];
    pa1 = *(const float4*)&emb[e1 + aslot];
    pw0 = *(const float4*)&Wxh[(size_t)(0  + wrow) * H_ + n0 + wcol];
    pw1 = *(const float4*)&Wxh[(size_t)(8  + wrow) * H_ + n0 + wcol];
    pw2 = *(const float4*)&Wxh[(size_t)(16 + wrow) * H_ + n0 + wcol];
    pw3 = *(const float4*)&Wxh[(size_t)(24 + wrow) * H_ + n0 + wcol];
    *(float4*)&AsB[arow * PAST + aslot]        = pa0;
    *(float4*)&AsB[(arow + 32) * PAST + aslot] = pa1;
    *(float4*)&WsB[(0  + wrow) * 128 + wcol] = pw0;
    *(float4*)&WsB[(8  + wrow) * 128 + wcol] = pw1;
    *(float4*)&WsB[(16 + wrow) * 128 + wcol] = pw2;
    *(float4*)&WsB[(24 + wrow) * 128 + wcol] = pw3;
    __syncthreads();

#pragma unroll 1
    for (int ch = 0; ch < 16; ch++) {
        if (ch < 15) {
            const int kn = (ch + 1) * 32;
            pa0 = *(const float4*)&emb[e0 + kn + aslot];
            pa1 = *(const float4*)&emb[e1 + kn + aslot];
            pw0 = *(const float4*)&Wxh[(size_t)(kn + wrow) * H_ + n0 + wcol];
            pw1 = *(const float4*)&Wxh[(size_t)(kn + 8  + wrow) * H_ + n0 + wcol];
            pw2 = *(const float4*)&Wxh[(size_t)(kn + 16 + wrow) * H_ + n0 + wcol];
            pw3 = *(const float4*)&Wxh[(size_t)(kn + 24 + wrow) * H_ + n0 + wcol];
        }
        const float* Ab = AsB + (ch & 1) * (64 * PAST);
        const float* Wb = WsB + (ch & 1) * (32 * 128);

#pragma unroll
        for (int kg = 0; kg < 8; kg++) {
            float4 a0 = *(const float4*)&Ab[(row0 + 0) * PAST + kg * 4];
            float4 a1 = *(const float4*)&Ab[(row0 + 1) * PAST + kg * 4];
            float4 a2 = *(const float4*)&Ab[(row0 + 2) * PAST + kg * 4];
            float4 a3 = *(const float4*)&Ab[(row0 + 3) * PAST + kg * 4];
            float4 a4 = *(const float4*)&Ab[(row0 + 4) * PAST + kg * 4];
            float4 a5 = *(const float4*)&Ab[(row0 + 5) * PAST + kg * 4];
            float4 a6 = *(const float4*)&Ab[(row0 + 6) * PAST + kg * 4];
            float4 a7 = *(const float4*)&Ab[(row0 + 7) * PAST + kg * 4];
#define PKJ(j, comp) {                                              \
            const u64* wp = (const u64*)&Wb[(kg * 4 + (j)) * 128 + c4]; \
            u64 w01 = wp[0], w23 = wp[1];                           \
            fma2(acc[0][0], splat2(a0.comp), w01); fma2(acc[0][1], splat2(a0.comp), w23); \
            fma2(acc[1][0], splat2(a1.comp), w01); fma2(acc[1][1], splat2(a1.comp), w23); \
            fma2(acc[2][0], splat2(a2.comp), w01); fma2(acc[2][1], splat2(a2.comp), w23); \
            fma2(acc[3][0], splat2(a3.comp), w01); fma2(acc[3][1], splat2(a3.comp), w23); \
            fma2(acc[4][0], splat2(a4.comp), w01); fma2(acc[4][1], splat2(a4.comp), w23); \
            fma2(acc[5][0], splat2(a5.comp), w01); fma2(acc[5][1], splat2(a5.comp), w23); \
            fma2(acc[6][0], splat2(a6.comp), w01); fma2(acc[6][1], splat2(a6.comp), w23); \
            fma2(acc[7][0], splat2(a7.comp), w01); fma2(acc[7][1], splat2(a7.comp), w23); }
            PKJ(0, x) PKJ(1, y) PKJ(2, z) PKJ(3, w)
#undef PKJ
        }

        if (ch < 15) {
            float* An = AsB + ((ch + 1) & 1) * (64 * PAST);
            float* Wn = WsB + ((ch + 1) & 1) * (32 * 128);
            *(float4*)&An[arow * PAST + aslot]        = pa0;
            *(float4*)&An[(arow + 32) * PAST + aslot] = pa1;
            *(float4*)&Wn[(0  + wrow) * 128 + wcol] = pw0;
            *(float4*)&Wn[(8  + wrow) * 128 + wcol] = pw1;
            *(float4*)&Wn[(16 + wrow) * 128 + wcol] = pw2;
            *(float4*)&Wn[(24 + wrow) * 128 + wcol] = pw3;
            __syncthreads();
        }
    }

    float4 bxv = *(const float4*)&bxh[n0 + c4];
    float4 bhv = *(const float4*)&bhh[n0 + c4];
    const float b0 = bxv.x + bhv.x, b1 = bxv.y + bhv.y;
    const float b2 = bxv.z + bhv.z, b3 = bxv.w + bhv.w;
#pragma unroll
    for (int i = 0; i < 8; i++) {
        float2 v0 = u2f(acc[i][0]);
        float2 v1 = u2f(acc[i][1]);
        float4 o; o.x = v0.x + b0; o.y = v0.y + b1; o.z = v1.x + b2; o.w = v1.y + b3;
        int m = m0 + row0 + i;
        int bb = m / S_;
        int tt = m - bb * S_;
        *(float4*)&g_P[((size_t)tt * B_ + bb) * H_ + n0 + c4] = o;
    }
}

// ============================================================================
// Kernel B: persistent RNN — two DECOUPLED M-groups per CTA.
// 128 CTAs = 8 pairs x 16 ranks (32 cols). Threads 0-127 run group 2p,
// threads 128-255 run group 2p+1 — fully independent recurrences with
// SEPARATE named barriers (bar.sync 1/2, 128) and SEPARATE flag spinners,
// so one half's publish/spin/restage latency hides behind the other half's
// compute. W col-pair-major u64 in smem; thread = 2 rows x 2 cols.
// ============================================================================
#define WST 514   // u64 stride for Wp rows
#define AST 516   // float stride for h staging rows
#define RNN_SMEM (16 * WST * 8 + 2 * 16 * AST * 4)  // 65792 + 66048 = 131840 B

__global__ __launch_bounds__(256, 1) void rnn_kernel(const float* __restrict__ Whh)
{
    extern __shared__ char smraw[];
    u64*   Wp  = (u64*)smraw;                       // [16][WST] u64
    float* AsA = (float*)(smraw + 16 * WST * 8);    // [16][AST]
    float* AsB = AsA + 16 * AST;                    // [16][AST]

    const int p  = blockIdx.x >> 4;       // group-pair 0..7
    const int r  = blockIdx.x & 15;       // N-rank 0..15
    const int n0 = 32 * r;
    const int t  = threadIdx.x;
    const int w  = t >> 5, l = t & 31;
    const int grp = w >> 2;               // 0: threads 0-127, 1: threads 128-255
    const int wg  = w & 3;                // warp-in-half
    const int g   = 2 * p + grp;          // my M-group
    const int rp  = l >> 3;               // 0..3 row-pair within warp
    const int cp  = (l & 7) + 8 * (wg >> 1);   // 0..15 col-pair
    const int row0 = 8 * (wg & 1) + 2 * rp;    // local row (even)
    float* As = grp ? AsB : AsA;
    const int bid = 1 + grp;              // named barrier id for this half

    const int grow0 = g * 16 + row0;
    const int gcol  = n0 + 2 * cp;

    // ---- load Whh slice col-pair-major: Wp[cp][k] = (Whh[k][n0+2cp], [k][n0+2cp+1])
    for (int idx = t; idx < 16 * 512; idx += 256) {
        int cpi = idx & 15, k = idx >> 4;
        Wp[cpi * WST + k] = *(const u64*)&Whh[(size_t)k * H_ + n0 + 2 * cpi];
    }
    // h(0) = 0
    for (int i = t; i < 16 * AST; i += 256) { AsA[i] = 0.0f; AsB[i] = 0.0f; }
    __syncthreads();   // before halves diverge

    float2 ps0 = {0, 0}, ps1 = {0, 0};

    const size_t pstride = (size_t)B_ * H_;
    const size_t pb0 = (size_t)grow0 * H_ + gcol;
    const size_t pb1 = pb0 + H_;
    u64 pP0 = *(const u64*)&g_P[pb0];
    u64 pP1 = *(const u64*)&g_P[pb1];

    unsigned* const cnt = &g_flags[g * 32];    // my group's counter
    const int ht = t & 127;                    // thread id within half
    const int gbase = g * 16;
    const bool leader = (ht == 0);

    for (int step = 0; step < S_; step++) {
        u64 acc0 = pP0, acc1 = pP1;
        if (step + 1 < S_) {
            const size_t po = (size_t)(step + 1) * pstride;
            pP0 = *(const u64*)&g_P[pb0 + po];
            pP1 = *(const u64*)&g_P[pb1 + po];
        }

        const float* ap0 = As + row0 * AST;
        const float* ap1 = ap0 + AST;
        const u64*  wp  = Wp + cp * WST;
#pragma unroll 4
        for (int k = 0; k < H_; k += 4) {
            float4 A0 = *(const float4*)(ap0 + k);
            float4 A1 = *(const float4*)(ap1 + k);
            ulonglong2 w01 = *(const ulonglong2*)(wp + k);
            ulonglong2 w23 = *(const ulonglong2*)(wp + k + 2);
            fma2(acc0, splat2(A0.x), w01.x); fma2(acc1, splat2(A1.x), w01.x);
            fma2(acc0, splat2(A0.y), w01.y); fma2(acc1, splat2(A1.y), w01.y);
            fma2(acc0, splat2(A0.z), w23.x); fma2(acc1, splat2(A1.z), w23.x);
            fma2(acc0, splat2(A0.w), w23.y); fma2(acc1, splat2(A1.w), w23.y);
        }

        // relu + pool
        float2 o0 = u2f(acc0), o1 = u2f(acc1);
        o0.x = fmaxf(o0.x, 0.f); o0.y = fmaxf(o0.y, 0.f);
        o1.x = fmaxf(o1.x, 0.f); o1.y = fmaxf(o1.y, 0.f);
        ps0.x += o0.x; ps0.y += o0.y; ps1.x += o1.x; ps1.y += o1.y;

        if (step + 1 < S_) {
            // publish own group's slice
            float* hdst = g_h[(step + 1) & 1];
            *(float2*)&hdst[pb0] = o0;
            *(float2*)&hdst[pb1] = o1;
            asm volatile("bar.sync %0, 128;" :: "r"(bid) : "memory");
            if (leader) {
                asm volatile("red.release.gpu.add.u32 [%0], 1;" :: "l"(cnt) : "memory");
                const unsigned tgt = 16u * (unsigned)(step + 1);
                unsigned v;
                do {
                    asm volatile("ld.acquire.gpu.u32 %0, [%1];" : "=r"(v) : "l"(cnt) : "memory");
                } while (v < tgt);
            }
            asm volatile("bar.sync %0, 128;" :: "r"(bid) : "memory");
            // restage own group's 16x512 h rows (half = 128 threads, 16 reps)
            const float* hsrc = g_h[(step + 1) & 1];
#pragma unroll
            for (int rep = 0; rep < 16; rep++) {
                int i4   = rep * 128 + ht;
                int arow = i4 >> 7;
                int k4   = (i4 & 127) * 4;
                *(float4*)&As[arow * AST + k4] =
                    *(const float4*)&hsrc[(size_t)(gbase + arow) * H_ + k4];
            }
            asm volatile("bar.sync %0, 128;" :: "r"(bid) : "memory");
        }
    }

    const float inv = 1.0f / (float)S_;
    float2 q;
    q.x = ps0.x * inv; q.y = ps0.y * inv; *(float2*)&g_pool[pb0] = q;
    q.x = ps1.x * inv; q.y = ps1.y * inv; *(float2*)&g_pool[pb1] = q;
}

// ============================================================================
// Kernel C: out = pooled @ Wfc + bfc
// ============================================================================
__global__ __launch_bounds__(128) void fc_kernel(const float* __restrict__ Wfc,
                                                 const float* __restrict__ bfc,
                                                 float* __restrict__ out)
{
    const int b = blockIdx.x;
    const int t = threadIdx.x;
    float s0 = 0, s1 = 0, s2 = 0, s3 = 0;
    const float* pr = &g_pool[(size_t)b * H_];
    for (int k = t; k < H_; k += 128) {
        float v = pr[k];
        float4 wv = *(const float4*)&Wfc[k * 4];
        s0 += v * wv.x; s1 += v * wv.y; s2 += v * wv.z; s3 += v * wv.w;
    }
#pragma unroll
    for (int o = 16; o > 0; o >>= 1) {
        s0 += __shfl_down_sync(0xffffffffu, s0, o);
        s1 += __shfl_down_sync(0xffffffffu, s1, o);
        s2 += __shfl_down_sync(0xffffffffu, s2, o);
        s3 += __shfl_down_sync(0xffffffffu, s3, o);
    }
    __shared__ float red[4][4];
    if ((t & 31) == 0) {
        int wrp = t >> 5;
        red[wrp][0] = s0; red[wrp][1] = s1; red[wrp][2] = s2; red[wrp][3] = s3;
    }
    __syncthreads();
    if (t < 4) {
        out[b * 4 + t] = red[0][t] + red[1][t] + red[2][t] + red[3][t] + bfc[t];
    }
}

// ============================================================================
extern "C" void kernel_launch(void* const* d_in, const int* in_sizes, int n_in,
                              void* d_out, int out_size)
{
    const int*   x   = (const int*)d_in[0];
    const float* emb = (const float*)d_in[1];
    const float* Wxh = (const float*)d_in[2];
    const float* bxh = (const float*)d_in[3];
    const float* Whh = (const float*)d_in[4];
    const float* bhh = (const float*)d_in[5];
    const float* Wfc = (const float*)d_in[6];
    const float* bfc = (const float*)d_in[7];
    float* out = (float*)d_out;

    void *hAddr = nullptr, *flagAddr = nullptr;
    cudaGetSymbolAddress(&hAddr, g_h);
    cudaGetSymbolAddress(&flagAddr, g_flags);
    cudaMemsetAsync(hAddr, 0, sizeof(float) * 2 * B_ * H_);
    cudaMemsetAsync(flagAddr, 0, sizeof(unsigned) * 16 * 32);

    cudaFuncSetAttribute(precompute_kernel, cudaFuncAttributeMaxDynamicSharedMemorySize, PC_SMEM);
    cudaFuncSetAttribute(rnn_kernel, cudaFuncAttributeMaxDynamicSharedMemorySize, RNN_SMEM);

    precompute_kernel<<<dim3(4, 800), 256, PC_SMEM>>>(x, emb, Wxh, bxh, bhh);
    rnn_kernel<<<128, 256, RNN_SMEM>>>(Whh);
    fc_kernel<<<B_, 128>>>(Wfc, bfc, out);
}